// round 1
// baseline (speedup 1.0000x reference)
#include <cuda_runtime.h>
#include <math.h>

#define B_  16
#define S_  1024
#define E_  1024
#define F_  4096
#define H_  16
#define D_  64
#define M_  (B_*S_)   // 16384 rows

// ---------------- scratch (device globals: allocation-free) ----------------
__device__ float g_xn [(size_t)M_*E_];      //  64 MB  layernorm output
__device__ float g_qkv[(size_t)M_*3*E_];    // 192 MB  qkv projection
__device__ float g_ctx[(size_t)M_*E_];      //  64 MB  attention context
__device__ float g_x1 [(size_t)M_*E_];      //  64 MB  post-attention residual
__device__ float g_h  [(size_t)M_*F_];      // 256 MB  ffn hidden

// ---------------- helpers ----------------
__device__ __forceinline__ unsigned f2tf32(float x) {
    unsigned u;
    asm("cvt.rna.tf32.f32 %0, %1;" : "=r"(u) : "f"(x));
    return u;
}
__device__ __forceinline__ float tf32f(float x) {
    return __uint_as_float(f2tf32(x));
}
__device__ __forceinline__ void mma_tf32(float c[4], const unsigned a[4], const unsigned b[2]) {
    asm volatile(
        "mma.sync.aligned.m16n8k8.row.col.f32.tf32.tf32.f32 "
        "{%0,%1,%2,%3}, {%4,%5,%6,%7}, {%8,%9}, {%0,%1,%2,%3};\n"
        : "+f"(c[0]), "+f"(c[1]), "+f"(c[2]), "+f"(c[3])
        : "r"(a[0]), "r"(a[1]), "r"(a[2]), "r"(a[3]), "r"(b[0]), "r"(b[1]));
}
__device__ __forceinline__ void cp_async16(unsigned dst, const void* src) {
    asm volatile("cp.async.cg.shared.global [%0], [%1], 16;\n" :: "r"(dst), "l"(src));
}

// ---------------- layernorm: one block per row, E=1024 ----------------
__global__ __launch_bounds__(256) void ln_kernel(
    const float* __restrict__ x, const float* __restrict__ w,
    const float* __restrict__ b, float* __restrict__ y)
{
    int row = blockIdx.x;
    int tid = threadIdx.x;
    const float4* xr = (const float4*)(x + (size_t)row * E_);
    float4 v = xr[tid];
    float s = v.x + v.y + v.z + v.w;
    float q = v.x*v.x + v.y*v.y + v.z*v.z + v.w*v.w;
    #pragma unroll
    for (int o = 16; o; o >>= 1) {
        s += __shfl_xor_sync(0xffffffffu, s, o);
        q += __shfl_xor_sync(0xffffffffu, q, o);
    }
    __shared__ float ss[8], qq[8];
    if ((tid & 31) == 0) { ss[tid >> 5] = s; qq[tid >> 5] = q; }
    __syncthreads();
    s = 0.f; q = 0.f;
    #pragma unroll
    for (int i = 0; i < 8; i++) { s += ss[i]; q += qq[i]; }
    float mu  = s * (1.0f / E_);
    float var = q * (1.0f / E_) - mu * mu;
    float inv = rsqrtf(var + 1e-5f);
    float4 wv = ((const float4*)w)[tid];
    float4 bv = ((const float4*)b)[tid];
    float4 o4;
    o4.x = (v.x - mu) * inv * wv.x + bv.x;
    o4.y = (v.y - mu) * inv * wv.y + bv.y;
    o4.z = (v.z - mu) * inv * wv.z + bv.z;
    o4.w = (v.w - mu) * inv * wv.w + bv.w;
    ((float4*)(y + (size_t)row * E_))[tid] = o4;
}

// ---------------- NT GEMM: C[M,N] = A[M,K] @ B[N,K]^T (+bias, epi) ----------------
// EPI: 0 = bias, 1 = bias + exact gelu, 2 = bias + residual add
#define BM 128
#define BN 128
#define BK 16

template<int EPI>
__global__ __launch_bounds__(256, 1) void gemm_nt(
    const float* __restrict__ A, const float* __restrict__ Bm,
    const float* __restrict__ bias, const float* __restrict__ res,
    float* __restrict__ C, int M, int N, int K)
{
    __shared__ float As[2][BM][BK + 4];
    __shared__ float Bs[2][BM][BK + 4];

    int tid  = threadIdx.x;
    int bm   = blockIdx.y * BM;
    int bn   = blockIdx.x * BN;
    int w    = tid >> 5, lane = tid & 31, g = lane >> 2, t = lane & 3;
    int wm   = (w >> 1) * 32;   // 4 warps along M
    int wn   = (w & 1) * 64;    // 2 warps along N

    float acc[2][8][4];
    #pragma unroll
    for (int i = 0; i < 2; i++)
        #pragma unroll
        for (int j = 0; j < 8; j++)
            #pragma unroll
            for (int k = 0; k < 4; k++) acc[i][j][k] = 0.f;

    int lr = tid >> 2;           // load row 0..63 within 256-float4 chunk step
    int lc = (tid & 3) * 4;      // load col (floats)

    // prologue: fill stage 0
    {
        #pragma unroll
        for (int i = 0; i < 2; i++) {
            int r = lr + i * 64;
            cp_async16((unsigned)__cvta_generic_to_shared(&As[0][r][lc]),
                       A + (size_t)(bm + r) * K + lc);
            cp_async16((unsigned)__cvta_generic_to_shared(&Bs[0][r][lc]),
                       Bm + (size_t)(bn + r) * K + lc);
        }
        asm volatile("cp.async.commit_group;\n");
    }

    int KT = K / BK;
    for (int kt = 0; kt < KT; kt++) {
        int st = kt & 1;
        if (kt + 1 < KT) {
            int k0 = (kt + 1) * BK;
            #pragma unroll
            for (int i = 0; i < 2; i++) {
                int r = lr + i * 64;
                cp_async16((unsigned)__cvta_generic_to_shared(&As[st ^ 1][r][lc]),
                           A + (size_t)(bm + r) * K + k0 + lc);
                cp_async16((unsigned)__cvta_generic_to_shared(&Bs[st ^ 1][r][lc]),
                           Bm + (size_t)(bn + r) * K + k0 + lc);
            }
            asm volatile("cp.async.commit_group;\n");
            asm volatile("cp.async.wait_group 1;\n");
        } else {
            asm volatile("cp.async.wait_group 0;\n");
        }
        __syncthreads();

        #pragma unroll
        for (int ks = 0; ks < 2; ks++) {
            int k8 = ks * 8;
            unsigned af[2][4], bf[8][2];
            #pragma unroll
            for (int mf = 0; mf < 2; mf++) {
                int rb = wm + mf * 16;
                af[mf][0] = f2tf32(As[st][rb + g    ][k8 + t    ]);
                af[mf][1] = f2tf32(As[st][rb + g + 8][k8 + t    ]);
                af[mf][2] = f2tf32(As[st][rb + g    ][k8 + t + 4]);
                af[mf][3] = f2tf32(As[st][rb + g + 8][k8 + t + 4]);
            }
            #pragma unroll
            for (int nf = 0; nf < 8; nf++) {
                int cb = wn + nf * 8;
                bf[nf][0] = f2tf32(Bs[st][cb + g][k8 + t    ]);
                bf[nf][1] = f2tf32(Bs[st][cb + g][k8 + t + 4]);
            }
            #pragma unroll
            for (int mf = 0; mf < 2; mf++)
                #pragma unroll
                for (int nf = 0; nf < 8; nf++)
                    mma_tf32(acc[mf][nf], af[mf], bf[nf]);
        }
        __syncthreads();
    }

    // epilogue
    #pragma unroll
    for (int mf = 0; mf < 2; mf++) {
        int r0 = bm + wm + mf * 16 + g;
        #pragma unroll
        for (int nf = 0; nf < 8; nf++) {
            int c0 = bn + wn + nf * 8 + 2 * t;
            float bz0 = bias[c0], bz1 = bias[c0 + 1];
            float v0 = acc[mf][nf][0] + bz0;
            float v1 = acc[mf][nf][1] + bz1;
            float v2 = acc[mf][nf][2] + bz0;
            float v3 = acc[mf][nf][3] + bz1;
            if (EPI == 1) {
                v0 = 0.5f * v0 * (1.0f + erff(v0 * 0.70710678118654752f));
                v1 = 0.5f * v1 * (1.0f + erff(v1 * 0.70710678118654752f));
                v2 = 0.5f * v2 * (1.0f + erff(v2 * 0.70710678118654752f));
                v3 = 0.5f * v3 * (1.0f + erff(v3 * 0.70710678118654752f));
            }
            if (EPI == 2) {
                v0 += res[(size_t)r0 * N + c0];
                v1 += res[(size_t)r0 * N + c0 + 1];
                v2 += res[(size_t)(r0 + 8) * N + c0];
                v3 += res[(size_t)(r0 + 8) * N + c0 + 1];
            }
            C[(size_t)r0 * N + c0]           = v0;
            C[(size_t)r0 * N + c0 + 1]       = v1;
            C[(size_t)(r0 + 8) * N + c0]     = v2;
            C[(size_t)(r0 + 8) * N + c0 + 1] = v3;
        }
    }
}

// ---------------- flash attention: per (b,h), 64 q-rows per block ----------------
// qkv row layout: [q(1024) | k(1024) | v(1024)], head h occupies cols h*64..h*64+63
__global__ __launch_bounds__(128, 1) void attn_kernel(
    const float* __restrict__ qkv, float* __restrict__ ctx)
{
    __shared__ float KP[64][68];   // K tile, later reused for P
    __shared__ float Vs[64][72];   // V tile (pad 8 for conflict-free b-frag loads)

    int bh = blockIdx.y;
    int b  = bh >> 4, h = bh & 15;
    int qt = blockIdx.x;
    int tid = threadIdx.x, w = tid >> 5, lane = tid & 31, g = lane >> 2, t = lane & 3;
    int rb = w * 16;

    const float* qp = qkv + (size_t)(b * S_ + qt * 64) * 3072 + h * 64;
    const float* kp = qkv + (size_t)(b * S_) * 3072 + E_ + h * 64;
    const float* vp = kp + E_;

    // stage Q (scaled by 1/sqrt(D) * log2(e), tf32-rounded) into KP
    const float qs = 0.125f * 1.4426950408889634f;
    #pragma unroll
    for (int i = 0; i < 8; i++) {
        int f = tid + i * 128;
        int r = f >> 4, c = (f & 15) * 4;
        float4 q4 = *(const float4*)(qp + (size_t)r * 3072 + c);
        KP[r][c + 0] = tf32f(q4.x * qs);
        KP[r][c + 1] = tf32f(q4.y * qs);
        KP[r][c + 2] = tf32f(q4.z * qs);
        KP[r][c + 3] = tf32f(q4.w * qs);
    }
    __syncthreads();

    // pull Q frags into registers (16 rows x 64 k per warp)
    unsigned qf[8][4];
    #pragma unroll
    for (int kc = 0; kc < 8; kc++) {
        qf[kc][0] = __float_as_uint(KP[rb + g    ][kc * 8 + t    ]);
        qf[kc][1] = __float_as_uint(KP[rb + g + 8][kc * 8 + t    ]);
        qf[kc][2] = __float_as_uint(KP[rb + g    ][kc * 8 + t + 4]);
        qf[kc][3] = __float_as_uint(KP[rb + g + 8][kc * 8 + t + 4]);
    }
    __syncthreads();

    float o[8][4];
    #pragma unroll
    for (int i = 0; i < 8; i++)
        #pragma unroll
        for (int j = 0; j < 4; j++) o[i][j] = 0.f;
    float m0 = -1e30f, m1 = -1e30f, l0 = 0.f, l1 = 0.f;

    for (int kt = 0; kt < 16; kt++) {
        const float* kb = kp + (size_t)kt * 64 * 3072;
        const float* vb = vp + (size_t)kt * 64 * 3072;
        #pragma unroll
        for (int i = 0; i < 8; i++) {
            int f = tid + i * 128;
            int r = f >> 4, c = (f & 15) * 4;
            float4 k4 = *(const float4*)(kb + (size_t)r * 3072 + c);
            KP[r][c + 0] = tf32f(k4.x); KP[r][c + 1] = tf32f(k4.y);
            KP[r][c + 2] = tf32f(k4.z); KP[r][c + 3] = tf32f(k4.w);
            float4 v4 = *(const float4*)(vb + (size_t)r * 3072 + c);
            Vs[r][c + 0] = tf32f(v4.x); Vs[r][c + 1] = tf32f(v4.y);
            Vs[r][c + 2] = tf32f(v4.z); Vs[r][c + 3] = tf32f(v4.w);
        }
        __syncthreads();

        // S = Q @ K^T (per warp: 16 x 64)
        float s[8][4];
        #pragma unroll
        for (int i = 0; i < 8; i++)
            #pragma unroll
            for (int j = 0; j < 4; j++) s[i][j] = 0.f;
        #pragma unroll
        for (int kc = 0; kc < 8; kc++) {
            unsigned bf[8][2];
            #pragma unroll
            for (int nf = 0; nf < 8; nf++) {
                bf[nf][0] = __float_as_uint(KP[nf * 8 + g][kc * 8 + t    ]);
                bf[nf][1] = __float_as_uint(KP[nf * 8 + g][kc * 8 + t + 4]);
            }
            #pragma unroll
            for (int nf = 0; nf < 8; nf++) mma_tf32(s[nf], qf[kc], bf[nf]);
        }

        // online softmax (exp2 domain)
        float mx0 = -1e30f, mx1 = -1e30f;
        #pragma unroll
        for (int nf = 0; nf < 8; nf++) {
            mx0 = fmaxf(mx0, fmaxf(s[nf][0], s[nf][1]));
            mx1 = fmaxf(mx1, fmaxf(s[nf][2], s[nf][3]));
        }
        mx0 = fmaxf(mx0, __shfl_xor_sync(0xffffffffu, mx0, 1));
        mx0 = fmaxf(mx0, __shfl_xor_sync(0xffffffffu, mx0, 2));
        mx1 = fmaxf(mx1, __shfl_xor_sync(0xffffffffu, mx1, 1));
        mx1 = fmaxf(mx1, __shfl_xor_sync(0xffffffffu, mx1, 2));
        float mn0 = fmaxf(m0, mx0), mn1 = fmaxf(m1, mx1);
        float a0 = exp2f(m0 - mn0), a1 = exp2f(m1 - mn1);
        m0 = mn0; m1 = mn1;

        float sum0 = 0.f, sum1 = 0.f;
        #pragma unroll
        for (int nf = 0; nf < 8; nf++) {
            float p0 = exp2f(s[nf][0] - m0);
            float p1 = exp2f(s[nf][1] - m0);
            float p2 = exp2f(s[nf][2] - m1);
            float p3 = exp2f(s[nf][3] - m1);
            sum0 += p0 + p1; sum1 += p2 + p3;
            s[nf][0] = p0; s[nf][1] = p1; s[nf][2] = p2; s[nf][3] = p3;
        }
        sum0 += __shfl_xor_sync(0xffffffffu, sum0, 1);
        sum0 += __shfl_xor_sync(0xffffffffu, sum0, 2);
        sum1 += __shfl_xor_sync(0xffffffffu, sum1, 1);
        sum1 += __shfl_xor_sync(0xffffffffu, sum1, 2);
        l0 = l0 * a0 + sum0;
        l1 = l1 * a1 + sum1;
        #pragma unroll
        for (int nf = 0; nf < 8; nf++) {
            o[nf][0] *= a0; o[nf][1] *= a0;
            o[nf][2] *= a1; o[nf][3] *= a1;
        }

        __syncthreads();   // all warps done reading K before overwriting with P
        #pragma unroll
        for (int nf = 0; nf < 8; nf++) {
            KP[rb + g    ][nf * 8 + 2 * t    ] = tf32f(s[nf][0]);
            KP[rb + g    ][nf * 8 + 2 * t + 1] = tf32f(s[nf][1]);
            KP[rb + g + 8][nf * 8 + 2 * t    ] = tf32f(s[nf][2]);
            KP[rb + g + 8][nf * 8 + 2 * t + 1] = tf32f(s[nf][3]);
        }
        __syncwarp();

        // O += P @ V (per warp: 16 x 64, k over the 64 kv rows)
        #pragma unroll
        for (int kc = 0; kc < 8; kc++) {
            unsigned af[4];
            af[0] = __float_as_uint(KP[rb + g    ][kc * 8 + t    ]);
            af[1] = __float_as_uint(KP[rb + g + 8][kc * 8 + t    ]);
            af[2] = __float_as_uint(KP[rb + g    ][kc * 8 + t + 4]);
            af[3] = __float_as_uint(KP[rb + g + 8][kc * 8 + t + 4]);
            #pragma unroll
            for (int nf = 0; nf < 8; nf++) {
                unsigned bf[2];
                bf[0] = __float_as_uint(Vs[kc * 8 + t    ][nf * 8 + g]);
                bf[1] = __float_as_uint(Vs[kc * 8 + t + 4][nf * 8 + g]);
                mma_tf32(o[nf], af, bf);
            }
        }
        __syncthreads();   // before next tile overwrites KP/Vs
    }

    // write ctx[b*S + row, h*64 + col]
    float il0 = 1.0f / l0, il1 = 1.0f / l1;
    int r0 = qt * 64 + rb + g;
    float* cb = ctx + (size_t)(b * S_) * E_ + h * 64;
    #pragma unroll
    for (int nf = 0; nf < 8; nf++) {
        int c0 = nf * 8 + 2 * t;
        cb[(size_t)r0 * E_ + c0]           = o[nf][0] * il0;
        cb[(size_t)r0 * E_ + c0 + 1]       = o[nf][1] * il0;
        cb[(size_t)(r0 + 8) * E_ + c0]     = o[nf][2] * il1;
        cb[(size_t)(r0 + 8) * E_ + c0 + 1] = o[nf][3] * il1;
    }
}

// ---------------- host launcher ----------------
extern "C" void kernel_launch(void* const* d_in, const int* in_sizes, int n_in,
                              void* d_out, int out_size)
{
    (void)in_sizes; (void)n_in; (void)out_size;
    const float* x     = (const float*)d_in[0];
    const float* in_w  = (const float*)d_in[1];
    const float* in_b  = (const float*)d_in[2];
    const float* out_w = (const float*)d_in[3];
    const float* out_b = (const float*)d_in[4];
    const float* l1w   = (const float*)d_in[5];
    const float* l1b   = (const float*)d_in[6];
    const float* l2w   = (const float*)d_in[7];
    const float* l2b   = (const float*)d_in[8];
    const float* n1w   = (const float*)d_in[9];
    const float* n1b   = (const float*)d_in[10];
    const float* n2w   = (const float*)d_in[11];
    const float* n2b   = (const float*)d_in[12];
    float* out = (float*)d_out;

    float *xn, *qkvb, *ctx, *x1, *hb;
    cudaGetSymbolAddress((void**)&xn,   g_xn);
    cudaGetSymbolAddress((void**)&qkvb, g_qkv);
    cudaGetSymbolAddress((void**)&ctx,  g_ctx);
    cudaGetSymbolAddress((void**)&x1,   g_x1);
    cudaGetSymbolAddress((void**)&hb,   g_h);

    // 1. xn = LN1(x)
    ln_kernel<<<M_, 256>>>(x, n1w, n1b, xn);
    // 2. qkv = xn @ in_proj_w^T + in_proj_b   [16384, 3072]
    gemm_nt<0><<<dim3(3 * E_ / BN, M_ / BM), 256>>>(xn, in_w, in_b, nullptr, qkvb, M_, 3 * E_, E_);
    // 3. ctx = flash-attention(qkv)           [16384, 1024]
    attn_kernel<<<dim3(S_ / 64, B_ * H_), 128>>>(qkvb, ctx);
    // 4. x1 = x + ctx @ out_w^T + out_b
    gemm_nt<2><<<dim3(E_ / BN, M_ / BM), 256>>>(ctx, out_w, out_b, x, x1, M_, E_, E_);
    // 5. xn = LN2(x1)
    ln_kernel<<<M_, 256>>>(x1, n2w, n2b, xn);
    // 6. h = gelu(xn @ lin1_w^T + lin1_b)     [16384, 4096]
    gemm_nt<1><<<dim3(F_ / BN, M_ / BM), 256>>>(xn, l1w, l1b, nullptr, hb, M_, F_, E_);
    // 7. out = x1 + h @ lin2_w^T + lin2_b
    gemm_nt<2><<<dim3(E_ / BN, M_ / BM), 256>>>(hb, l2w, l2b, x1, out, M_, E_, F_);
}